// round 12
// baseline (speedup 1.0000x reference)
#include <cuda_runtime.h>
#include <cstdint>

// ---------------------------------------------------------------------------
// Fused causal attention head via warp-level tf32 mma.sync. One CTA per batch,
// 2 CTAs/SM. Permuted-k mapping (lane q4 carries k=2q4,2q4+1 on A and B) makes
// accumulator layout == A-fragment layout. R12: register-resident operands
// (X frags, Q, P) are fed RAW to the mma (HW tf32 truncation), and the
// systematic truncation bias (~2^-11.5 low, multiplicative) is CANCELLED by
// pre-scaling the weights: W* x (1+eps) per truncation stage (Wq gets two
// stages: X-trunc at projection + Q-trunc at S). P's bias self-cancels via
// softmax normalization. SMEM-bound data (W, K, V) stays round-to-nearest.
//   x:[4096,128,64] f32, Wq/Wk/Wv:[64,64] f32, out:[4096,128,64] f32
// ---------------------------------------------------------------------------

#define DEVINL __device__ __forceinline__

static constexpr int T = 128;
static constexpr int C = 64;
static constexpr int H = 64;

// mean tf32-truncation bias compensation (one stage): 1 + 2^-11.5
static constexpr float CMP1 = 1.000345f;
static constexpr float CMP2 = CMP1 * CMP1;   // two truncation stages (Wq)

static constexpr int RST = 72;    // row stride (words) W / K   (72  % 32 == 8)
static constexpr int VST = 136;   // row stride (words) V^T     (136 % 32 == 8)

static constexpr uint32_t WSZ  = 64 * RST * 4;            // 18432 per W matrix
static constexpr uint32_t SM_W = 0;                       // Wk@0, Wv@18432
static constexpr uint32_t SM_K = 2 * WSZ;                 // 36864: Wq staged here, then K
static constexpr uint32_t SM_V = SM_K + 128 * RST * 4;    // 73728: V^T 64x136
static constexpr uint32_t SM_TOT = SM_V + 64 * VST * 4;   // 108544 -> 2 CTAs/SM

DEVINL uint32_t f2tf(float f) {
    uint32_t r; asm("cvt.rna.tf32.f32 %0, %1;" : "=r"(r) : "f"(f)); return r;
}
DEVINL float ex2f(float x) {
    float y; asm("ex2.approx.ftz.f32 %0, %1;" : "=f"(y) : "f"(x)); return y;
}
DEVINL void sts32(uint32_t a, uint32_t v) {
    asm volatile("st.shared.b32 [%0], %1;" :: "r"(a), "r"(v) : "memory");
}
DEVINL void sts64(uint32_t a, uint32_t v0, uint32_t v1) {
    asm volatile("st.shared.v2.b32 [%0], {%1,%2};" :: "r"(a), "r"(v0), "r"(v1) : "memory");
}
DEVINL void sts128(uint32_t a, uint32_t r0, uint32_t r1, uint32_t r2, uint32_t r3) {
    asm volatile("st.shared.v4.b32 [%0], {%1,%2,%3,%4};"
                 :: "r"(a), "r"(r0), "r"(r1), "r"(r2), "r"(r3) : "memory");
}
DEVINL uint2 lds64(uint32_t a) {
    uint2 v;
    asm volatile("ld.shared.v2.b32 {%0,%1}, [%2];" : "=r"(v.x), "=r"(v.y) : "r"(a));
    return v;
}

// D += A(16x8) * B(8x8), tf32, fp32 accum.
// Permuted-k convention: frag slot q4 carries k=2q4, slot q4+4 carries k=2q4+1.
DEVINL void mma8(float d[4], const uint32_t a[4], uint32_t b0, uint32_t b1) {
    asm volatile(
        "mma.sync.aligned.m16n8k8.row.col.f32.tf32.tf32.f32 "
        "{%0,%1,%2,%3}, {%4,%5,%6,%7}, {%8,%9}, {%0,%1,%2,%3};"
        : "+f"(d[0]), "+f"(d[1]), "+f"(d[2]), "+f"(d[3])
        : "r"(a[0]), "r"(a[1]), "r"(a[2]), "r"(a[3]), "r"(b0), "r"(b1));
}

extern "C" __global__ void __launch_bounds__(256, 2)
attn_head_kernel(const float* __restrict__ xg, const float* __restrict__ wqg,
                 const float* __restrict__ wkg, const float* __restrict__ wvg,
                 float* __restrict__ outg)
{
    extern __shared__ __align__(16) char smc[];
    const uint32_t sm = [&] { uint32_t a;
        asm("{ .reg .u64 t; cvta.to.shared.u64 t, %1; cvt.u32.u64 %0, t; }"
            : "=r"(a) : "l"(smc)); return a; }();
    const int tid  = threadIdx.x;
    const int lane = tid & 31;
    const int w    = tid >> 5;          // warp 0..7
    const int b    = blockIdx.x;
    const int g    = lane >> 2;         // group id 0..7
    const int q4   = lane & 3;          // thread-in-group 0..3
    const int r_lo = 16 * w + g;        // CTA-local rows owned by this lane
    const int r_hi = r_lo + 8;

    // ---- X A-fragments straight from gmem: LDG.64 float2, RAW fp32 bits
    //      (tf32 mma truncates in HW; bias compensated inside W). ----
    const float2* xb2 = reinterpret_cast<const float2*>(xg + (size_t)b * T * C);
    uint32_t ax[8][4];
    #pragma unroll
    for (int kt = 0; kt < 8; kt++) {
        float2 lo = xb2[r_lo * 32 + kt * 4 + q4];
        float2 hi = xb2[r_hi * 32 + kt * 4 + q4];
        ax[kt][0] = __float_as_uint(lo.x);   // (r_lo, 2q4)
        ax[kt][1] = __float_as_uint(hi.x);   // (r_hi, 2q4)
        ax[kt][2] = __float_as_uint(lo.y);   // (r_lo, 2q4+1)
        ax[kt][3] = __float_as_uint(hi.y);   // (r_hi, 2q4+1)
    }

    // ---- Stage Wk@0, Wv@18432, Wq@SM_K (rounded tf32, bias-compensated).
    //      Wq also folds 1/sqrt(64) and the Q-truncation stage. ----
    #pragma unroll
    for (int m = 0; m < 3; m++) {
        const float4* wp4 = reinterpret_cast<const float4*>(
            (m == 0) ? wkg : ((m == 1) ? wvg : wqg));
        const uint32_t base = sm + ((m == 2) ? SM_K : m * WSZ);
        const float sc = (m == 2) ? 0.125f * CMP2 : CMP1;
        #pragma unroll
        for (int j = 0; j < 4; j++) {
            int i = tid + j * 256;          // 0..1023 float4
            int row = i >> 4, c4 = i & 15;
            float4 v = wp4[i];
            sts128(base + (row * RST + c4 * 4) * 4,
                   f2tf(v.x * sc), f2tf(v.y * sc), f2tf(v.z * sc), f2tf(v.w * sc));
        }
    }
    __syncthreads();

    // ---- Q = X*Wq^T -> registers (accumulator layout; Wq lives in SM_K) ----
    float q[8][4];
    #pragma unroll
    for (int nt = 0; nt < 8; nt++) {
        q[nt][0] = q[nt][1] = q[nt][2] = q[nt][3] = 0.f;
        #pragma unroll
        for (int kt = 0; kt < 8; kt++) {
            uint2 bb = lds64(sm + SM_K + ((nt * 8 + g) * RST + kt * 8 + 2 * q4) * 4);
            mma8(q[nt], ax[kt], bb.x, bb.y);
        }
    }
    __syncthreads();   // all warps done reading Wq before K overwrites SM_K

    // ---- K = X*Wk^T -> SM_K (row-major), V = X*Wv^T -> SM_V (V^T row-major) ----
    #pragma unroll
    for (int m = 0; m < 2; m++) {
        const uint32_t wbase = sm + m * WSZ;
        #pragma unroll
        for (int nt = 0; nt < 8; nt++) {
            float acc[4] = {0.f, 0.f, 0.f, 0.f};
            #pragma unroll
            for (int kt = 0; kt < 8; kt++) {
                uint2 bb = lds64(wbase + ((nt * 8 + g) * RST + kt * 8 + 2 * q4) * 4);
                mma8(acc, ax[kt], bb.x, bb.y);
            }
            if (m == 0) {
                // K[token][feat]: accum cols are adjacent -> STS.64 (rounded)
                sts64(sm + SM_K + (r_lo * RST + nt * 8 + 2 * q4) * 4,
                      f2tf(acc[0]), f2tf(acc[1]));
                sts64(sm + SM_K + (r_hi * RST + nt * 8 + 2 * q4) * 4,
                      f2tf(acc[2]), f2tf(acc[3]));
            } else {
                // V^T[feat][token]: feat = nt*8+2q4 (+1), token = r_lo / r_hi
                uint32_t f0 = sm + SM_V + ((nt * 8 + 2 * q4) * VST) * 4;
                sts32(f0 + r_lo * 4,           f2tf(acc[0]));
                sts32(f0 + (VST + r_lo) * 4,   f2tf(acc[1]));
                sts32(f0 + r_hi * 4,           f2tf(acc[2]));
                sts32(f0 + (VST + r_hi) * 4,   f2tf(acc[3]));
            }
        }
    }
    __syncthreads();   // K/V visible to all warps

    // ---- A-frags of Q: pure register permutation (raw; HW truncates,
    //      bias pre-compensated in Wq) ----
    uint32_t aq[8][4];
    #pragma unroll
    for (int kt = 0; kt < 8; kt++) {
        aq[kt][0] = __float_as_uint(q[kt][0]);   // (r_lo, 2q4)
        aq[kt][1] = __float_as_uint(q[kt][2]);   // (r_hi, 2q4)
        aq[kt][2] = __float_as_uint(q[kt][1]);   // (r_lo, 2q4+1)
        aq[kt][3] = __float_as_uint(q[kt][3]);   // (r_hi, 2q4+1)
    }

    // ---- Phase 2: S = Q * K^T (causal: skip fully-masked n-tiles) ----
    float s[16][4];
    #pragma unroll
    for (int nt = 0; nt < 16; nt++)
        s[nt][0] = s[nt][1] = s[nt][2] = s[nt][3] = 0.f;
    const int tile_max = 2 * w + 2;
    #pragma unroll
    for (int nt = 0; nt < 16; nt++) {
        if (nt < tile_max) {
            #pragma unroll
            for (int kt = 0; kt < 8; kt++) {
                uint2 bb = lds64(sm + SM_K + ((nt * 8 + g) * RST + kt * 8 + 2 * q4) * 4);
                mma8(s[nt], aq[kt], bb.x, bb.y);
            }
        }
    }

    // ---- Causal softmax in registers (row spread over a lane quad),
    //      loops bounded by tile_max ----
    float m_lo = -1e30f, m_hi = -1e30f;
    #pragma unroll
    for (int nt = 0; nt < 16; nt++) {
        if (nt < tile_max) {
            #pragma unroll
            for (int e = 0; e < 2; e++) {
                int col = nt * 8 + 2 * q4 + e;
                if (col <= r_lo) m_lo = fmaxf(m_lo, s[nt][e]);
                if (col <= r_hi) m_hi = fmaxf(m_hi, s[nt][2 + e]);
            }
        }
    }
    m_lo = fmaxf(m_lo, __shfl_xor_sync(~0u, m_lo, 1));
    m_lo = fmaxf(m_lo, __shfl_xor_sync(~0u, m_lo, 2));
    m_hi = fmaxf(m_hi, __shfl_xor_sync(~0u, m_hi, 1));
    m_hi = fmaxf(m_hi, __shfl_xor_sync(~0u, m_hi, 2));

    const float L2E = 1.4426950408889634f;
    float sum_lo = 0.f, sum_hi = 0.f;
    #pragma unroll
    for (int nt = 0; nt < 16; nt++) {
        if (nt < tile_max) {
            #pragma unroll
            for (int e = 0; e < 2; e++) {
                int col = nt * 8 + 2 * q4 + e;
                float pl = (col <= r_lo) ? ex2f((s[nt][e]     - m_lo) * L2E) : 0.f;
                float ph = (col <= r_hi) ? ex2f((s[nt][2 + e] - m_hi) * L2E) : 0.f;
                sum_lo += pl; sum_hi += ph;
                s[nt][e]     = pl;   // P raw fp32; truncation bias cancels in the
                s[nt][2 + e] = ph;   // normalization (num and den biased alike)
            }
        }
    }
    sum_lo += __shfl_xor_sync(~0u, sum_lo, 1);
    sum_lo += __shfl_xor_sync(~0u, sum_lo, 2);
    sum_hi += __shfl_xor_sync(~0u, sum_hi, 1);
    sum_hi += __shfl_xor_sync(~0u, sum_hi, 2);
    const float inv_lo = 1.f / sum_lo, inv_hi = 1.f / sum_hi;

    // ---- Phase 4: O = P * V. P A-frags = register permutation of s[] ----
    float o[8][4];
    #pragma unroll
    for (int nt = 0; nt < 8; nt++)
        o[nt][0] = o[nt][1] = o[nt][2] = o[nt][3] = 0.f;
    #pragma unroll
    for (int kt = 0; kt < 16; kt++) {
        if (kt < tile_max) {
            uint32_t ap[4];
            ap[0] = __float_as_uint(s[kt][0]);   // (r_lo, token 2q4)
            ap[1] = __float_as_uint(s[kt][2]);   // (r_hi, token 2q4)
            ap[2] = __float_as_uint(s[kt][1]);   // (r_lo, token 2q4+1)
            ap[3] = __float_as_uint(s[kt][3]);   // (r_hi, token 2q4+1)
            #pragma unroll
            for (int nt = 0; nt < 8; nt++) {
                uint2 bb = lds64(sm + SM_V + ((nt * 8 + g) * VST + kt * 8 + 2 * q4) * 4);
                mma8(o[nt], ap, bb.x, bb.y);
            }
        }
    }

    // ---- Normalize and store ----
    float* ob = outg + (size_t)b * T * H;
    #pragma unroll
    for (int nt = 0; nt < 8; nt++) {
        float2 vlo = make_float2(o[nt][0] * inv_lo, o[nt][1] * inv_lo);
        float2 vhi = make_float2(o[nt][2] * inv_hi, o[nt][3] * inv_hi);
        *reinterpret_cast<float2*>(ob + r_lo * 64 + nt * 8 + 2 * q4) = vlo;
        *reinterpret_cast<float2*>(ob + r_hi * 64 + nt * 8 + 2 * q4) = vhi;
    }
}

// ------------------------------ launcher -----------------------------------

extern "C" void kernel_launch(void* const* d_in, const int* in_sizes, int n_in,
                              void* d_out, int out_size) {
    const float* x  = (const float*)d_in[0];
    const float* wq = (const float*)d_in[1];
    const float* wk = (const float*)d_in[2];
    const float* wv = (const float*)d_in[3];
    float* out = (float*)d_out;
    const int nb = in_sizes[0] / (T * C);

    cudaFuncSetAttribute(attn_head_kernel,
                         cudaFuncAttributeMaxDynamicSharedMemorySize, (int)SM_TOT);
    attn_head_kernel<<<nb, 256, SM_TOT>>>(x, wq, wk, wv, out);
}

// round 13
// speedup vs baseline: 1.4845x; 1.4845x over previous
#include <cuda_runtime.h>
#include <cstdint>

// ---------------------------------------------------------------------------
// Fused causal attention head via warp-level tf32 mma.sync. One CTA per batch,
// 2 CTAs/SM. Permuted-k mapping (lane q4 carries k=2q4,2q4+1 on A and B) makes
// accumulator layout == A-fragment layout. R13 = R10 register structure with
// two proven-safe raw-truncation sites: X frags fed RAW (bias compensated by
// x(1+eps) folded into all W) and P fed RAW (bias cancels in softmax
// normalization). Q->aq keeps cvt.rna (kills q[]'s live range -- the R12
// zero-instruction permutation caused ptxas spills). Softmax loops are
// branch-free (full 16 iterations) for the same reason.
//   x:[4096,128,64] f32, Wq/Wk/Wv:[64,64] f32, out:[4096,128,64] f32
// ---------------------------------------------------------------------------

#define DEVINL __device__ __forceinline__

static constexpr int T = 128;
static constexpr int C = 64;
static constexpr int H = 64;

// mean tf32-truncation bias compensation (one stage): 1 + 2^-11.5
static constexpr float CMP1 = 1.000345f;

static constexpr int RST = 72;    // row stride (words) W / K   (72  % 32 == 8)
static constexpr int VST = 136;   // row stride (words) V^T     (136 % 32 == 8)

static constexpr uint32_t WSZ  = 64 * RST * 4;            // 18432 per W matrix
static constexpr uint32_t SM_W = 0;                       // Wk@0, Wv@18432
static constexpr uint32_t SM_K = 2 * WSZ;                 // 36864: Wq staged here, then K
static constexpr uint32_t SM_V = SM_K + 128 * RST * 4;    // 73728: V^T 64x136
static constexpr uint32_t SM_TOT = SM_V + 64 * VST * 4;   // 108544 -> 2 CTAs/SM

DEVINL uint32_t f2tf(float f) {
    uint32_t r; asm("cvt.rna.tf32.f32 %0, %1;" : "=r"(r) : "f"(f)); return r;
}
DEVINL float ex2f(float x) {
    float y; asm("ex2.approx.ftz.f32 %0, %1;" : "=f"(y) : "f"(x)); return y;
}
DEVINL void sts32(uint32_t a, uint32_t v) {
    asm volatile("st.shared.b32 [%0], %1;" :: "r"(a), "r"(v) : "memory");
}
DEVINL void sts64(uint32_t a, uint32_t v0, uint32_t v1) {
    asm volatile("st.shared.v2.b32 [%0], {%1,%2};" :: "r"(a), "r"(v0), "r"(v1) : "memory");
}
DEVINL void sts128(uint32_t a, uint32_t r0, uint32_t r1, uint32_t r2, uint32_t r3) {
    asm volatile("st.shared.v4.b32 [%0], {%1,%2,%3,%4};"
                 :: "r"(a), "r"(r0), "r"(r1), "r"(r2), "r"(r3) : "memory");
}
DEVINL uint2 lds64(uint32_t a) {
    uint2 v;
    asm volatile("ld.shared.v2.b32 {%0,%1}, [%2];" : "=r"(v.x), "=r"(v.y) : "r"(a));
    return v;
}

// D += A(16x8) * B(8x8), tf32, fp32 accum.
// Permuted-k convention: frag slot q4 carries k=2q4, slot q4+4 carries k=2q4+1.
DEVINL void mma8(float d[4], const uint32_t a[4], uint32_t b0, uint32_t b1) {
    asm volatile(
        "mma.sync.aligned.m16n8k8.row.col.f32.tf32.tf32.f32 "
        "{%0,%1,%2,%3}, {%4,%5,%6,%7}, {%8,%9}, {%0,%1,%2,%3};"
        : "+f"(d[0]), "+f"(d[1]), "+f"(d[2]), "+f"(d[3])
        : "r"(a[0]), "r"(a[1]), "r"(a[2]), "r"(a[3]), "r"(b0), "r"(b1));
}

extern "C" __global__ void __launch_bounds__(256, 2)
attn_head_kernel(const float* __restrict__ xg, const float* __restrict__ wqg,
                 const float* __restrict__ wkg, const float* __restrict__ wvg,
                 float* __restrict__ outg)
{
    extern __shared__ __align__(16) char smc[];
    const uint32_t sm = [&] { uint32_t a;
        asm("{ .reg .u64 t; cvta.to.shared.u64 t, %1; cvt.u32.u64 %0, t; }"
            : "=r"(a) : "l"(smc)); return a; }();
    const int tid  = threadIdx.x;
    const int lane = tid & 31;
    const int w    = tid >> 5;          // warp 0..7
    const int b    = blockIdx.x;
    const int g    = lane >> 2;         // group id 0..7
    const int q4   = lane & 3;          // thread-in-group 0..3
    const int r_lo = 16 * w + g;        // CTA-local rows owned by this lane
    const int r_hi = r_lo + 8;

    // ---- X A-fragments straight from gmem: LDG.64 float2, RAW fp32 bits
    //      (tf32 mma truncates in HW; bias compensated inside W). ----
    const float2* xb2 = reinterpret_cast<const float2*>(xg + (size_t)b * T * C);
    uint32_t ax[8][4];
    #pragma unroll
    for (int kt = 0; kt < 8; kt++) {
        float2 lo = xb2[r_lo * 32 + kt * 4 + q4];
        float2 hi = xb2[r_hi * 32 + kt * 4 + q4];
        ax[kt][0] = __float_as_uint(lo.x);   // (r_lo, 2q4)
        ax[kt][1] = __float_as_uint(hi.x);   // (r_hi, 2q4)
        ax[kt][2] = __float_as_uint(lo.y);   // (r_lo, 2q4+1)
        ax[kt][3] = __float_as_uint(hi.y);   // (r_hi, 2q4+1)
    }

    // ---- Stage Wk@0, Wv@18432, Wq@SM_K (rounded tf32, x CMP1 for the raw-X
    //      truncation stage; Wq also folds 1/sqrt(64)). ----
    #pragma unroll
    for (int m = 0; m < 3; m++) {
        const float4* wp4 = reinterpret_cast<const float4*>(
            (m == 0) ? wkg : ((m == 1) ? wvg : wqg));
        const uint32_t base = sm + ((m == 2) ? SM_K : m * WSZ);
        const float sc = (m == 2) ? 0.125f * CMP1 : CMP1;
        #pragma unroll
        for (int j = 0; j < 4; j++) {
            int i = tid + j * 256;          // 0..1023 float4
            int row = i >> 4, c4 = i & 15;
            float4 v = wp4[i];
            sts128(base + (row * RST + c4 * 4) * 4,
                   f2tf(v.x * sc), f2tf(v.y * sc), f2tf(v.z * sc), f2tf(v.w * sc));
        }
    }
    __syncthreads();

    // ---- Q = X*Wq^T -> registers (accumulator layout; Wq lives in SM_K) ----
    float q[8][4];
    #pragma unroll
    for (int nt = 0; nt < 8; nt++) {
        q[nt][0] = q[nt][1] = q[nt][2] = q[nt][3] = 0.f;
        #pragma unroll
        for (int kt = 0; kt < 8; kt++) {
            uint2 bb = lds64(sm + SM_K + ((nt * 8 + g) * RST + kt * 8 + 2 * q4) * 4);
            mma8(q[nt], ax[kt], bb.x, bb.y);
        }
    }
    __syncthreads();   // all warps done reading Wq before K overwrites SM_K

    // ---- K = X*Wk^T -> SM_K (row-major), V = X*Wv^T -> SM_V (V^T row-major) ----
    #pragma unroll
    for (int m = 0; m < 2; m++) {
        const uint32_t wbase = sm + m * WSZ;
        #pragma unroll
        for (int nt = 0; nt < 8; nt++) {
            float acc[4] = {0.f, 0.f, 0.f, 0.f};
            #pragma unroll
            for (int kt = 0; kt < 8; kt++) {
                uint2 bb = lds64(wbase + ((nt * 8 + g) * RST + kt * 8 + 2 * q4) * 4);
                mma8(acc, ax[kt], bb.x, bb.y);
            }
            if (m == 0) {
                // K[token][feat]: accum cols are adjacent -> STS.64 (rounded)
                sts64(sm + SM_K + (r_lo * RST + nt * 8 + 2 * q4) * 4,
                      f2tf(acc[0]), f2tf(acc[1]));
                sts64(sm + SM_K + (r_hi * RST + nt * 8 + 2 * q4) * 4,
                      f2tf(acc[2]), f2tf(acc[3]));
            } else {
                // V^T[feat][token]: feat = nt*8+2q4 (+1), token = r_lo / r_hi
                uint32_t f0 = sm + SM_V + ((nt * 8 + 2 * q4) * VST) * 4;
                sts32(f0 + r_lo * 4,           f2tf(acc[0]));
                sts32(f0 + (VST + r_lo) * 4,   f2tf(acc[1]));
                sts32(f0 + r_hi * 4,           f2tf(acc[2]));
                sts32(f0 + (VST + r_hi) * 4,   f2tf(acc[3]));
            }
        }
    }
    __syncthreads();   // K/V visible to all warps

    // ---- A-frags of Q: cvt.rna (rounded; also ends q[]'s live range) ----
    uint32_t aq[8][4];
    #pragma unroll
    for (int kt = 0; kt < 8; kt++) {
        aq[kt][0] = f2tf(q[kt][0]);   // (r_lo, 2q4)
        aq[kt][1] = f2tf(q[kt][2]);   // (r_hi, 2q4)
        aq[kt][2] = f2tf(q[kt][1]);   // (r_lo, 2q4+1)
        aq[kt][3] = f2tf(q[kt][3]);   // (r_hi, 2q4+1)
    }

    // ---- Phase 2: S = Q * K^T (causal: skip fully-masked n-tiles) ----
    float s[16][4];
    #pragma unroll
    for (int nt = 0; nt < 16; nt++)
        s[nt][0] = s[nt][1] = s[nt][2] = s[nt][3] = 0.f;
    const int tile_max = 2 * w + 2;
    #pragma unroll
    for (int nt = 0; nt < 16; nt++) {
        if (nt < tile_max) {
            #pragma unroll
            for (int kt = 0; kt < 8; kt++) {
                uint2 bb = lds64(sm + SM_K + ((nt * 8 + g) * RST + kt * 8 + 2 * q4) * 4);
                mma8(s[nt], aq[kt], bb.x, bb.y);
            }
        }
    }

    // ---- Causal softmax in registers (row spread over a lane quad),
    //      branch-free full loops (R10 structure) ----
    float m_lo = -1e30f, m_hi = -1e30f;
    #pragma unroll
    for (int nt = 0; nt < 16; nt++) {
        #pragma unroll
        for (int e = 0; e < 2; e++) {
            int col = nt * 8 + 2 * q4 + e;
            if (col <= r_lo) m_lo = fmaxf(m_lo, s[nt][e]);
            if (col <= r_hi) m_hi = fmaxf(m_hi, s[nt][2 + e]);
        }
    }
    m_lo = fmaxf(m_lo, __shfl_xor_sync(~0u, m_lo, 1));
    m_lo = fmaxf(m_lo, __shfl_xor_sync(~0u, m_lo, 2));
    m_hi = fmaxf(m_hi, __shfl_xor_sync(~0u, m_hi, 1));
    m_hi = fmaxf(m_hi, __shfl_xor_sync(~0u, m_hi, 2));

    const float L2E = 1.4426950408889634f;
    float sum_lo = 0.f, sum_hi = 0.f;
    #pragma unroll
    for (int nt = 0; nt < 16; nt++) {
        #pragma unroll
        for (int e = 0; e < 2; e++) {
            int col = nt * 8 + 2 * q4 + e;
            float pl = (col <= r_lo) ? ex2f((s[nt][e]     - m_lo) * L2E) : 0.f;
            float ph = (col <= r_hi) ? ex2f((s[nt][2 + e] - m_hi) * L2E) : 0.f;
            sum_lo += pl; sum_hi += ph;
            s[nt][e]     = pl;   // P raw fp32; truncation bias cancels in the
            s[nt][2 + e] = ph;   // normalization (num and den biased alike)
        }
    }
    sum_lo += __shfl_xor_sync(~0u, sum_lo, 1);
    sum_lo += __shfl_xor_sync(~0u, sum_lo, 2);
    sum_hi += __shfl_xor_sync(~0u, sum_hi, 1);
    sum_hi += __shfl_xor_sync(~0u, sum_hi, 2);
    const float inv_lo = 1.f / sum_lo, inv_hi = 1.f / sum_hi;

    // ---- Phase 4: O = P * V. P A-frags = register permutation of s[] ----
    float o[8][4];
    #pragma unroll
    for (int nt = 0; nt < 8; nt++)
        o[nt][0] = o[nt][1] = o[nt][2] = o[nt][3] = 0.f;
    #pragma unroll
    for (int kt = 0; kt < 16; kt++) {
        if (kt < tile_max) {
            uint32_t ap[4];
            ap[0] = __float_as_uint(s[kt][0]);   // (r_lo, token 2q4)
            ap[1] = __float_as_uint(s[kt][2]);   // (r_hi, token 2q4)
            ap[2] = __float_as_uint(s[kt][1]);   // (r_lo, token 2q4+1)
            ap[3] = __float_as_uint(s[kt][3]);   // (r_hi, token 2q4+1)
            #pragma unroll
            for (int nt = 0; nt < 8; nt++) {
                uint2 bb = lds64(sm + SM_V + ((nt * 8 + g) * VST + kt * 8 + 2 * q4) * 4);
                mma8(o[nt], ap, bb.x, bb.y);
            }
        }
    }

    // ---- Normalize and store ----
    float* ob = outg + (size_t)b * T * H;
    #pragma unroll
    for (int nt = 0; nt < 8; nt++) {
        float2 vlo = make_float2(o[nt][0] * inv_lo, o[nt][1] * inv_lo);
        float2 vhi = make_float2(o[nt][2] * inv_hi, o[nt][3] * inv_hi);
        *reinterpret_cast<float2*>(ob + r_lo * 64 + nt * 8 + 2 * q4) = vlo;
        *reinterpret_cast<float2*>(ob + r_hi * 64 + nt * 8 + 2 * q4) = vhi;
    }
}

// ------------------------------ launcher -----------------------------------

extern "C" void kernel_launch(void* const* d_in, const int* in_sizes, int n_in,
                              void* d_out, int out_size) {
    const float* x  = (const float*)d_in[0];
    const float* wq = (const float*)d_in[1];
    const float* wk = (const float*)d_in[2];
    const float* wv = (const float*)d_in[3];
    float* out = (float*)d_out;
    const int nb = in_sizes[0] / (T * C);

    cudaFuncSetAttribute(attn_head_kernel,
                         cudaFuncAttributeMaxDynamicSharedMemorySize, (int)SM_TOT);
    attn_head_kernel<<<nb, 256, SM_TOT>>>(x, wq, wk, wv, out);
}